// round 15
// baseline (speedup 1.0000x reference)
#include <cuda_runtime.h>
#include <cstdint>
#include <cstdio>

// Problem constants: B=8, P=784, D=384, N=16384
#define DD      384
#define M_ROWS  6272
#define N_CORE  16384
#define BSZ     8
#define PP      784
#define NK      9

#define BM      128
#define BN      256
#define BK      32
#define KCHUNKS (DD / BK)               // 12
#define NSPLIT  3
#define NT_ALL  (N_CORE / BN)           // 64 N-tiles
#define MBLKS   (M_ROWS / BM)           // 49

// smem bytes: A [2][128][32]f = 32768, B [2][32][256]f = 65536
#define OFF_B      32768
#define SMEM_TOTAL 98304

// ---------------- device scratch (no allocations allowed) ----------------
// C transposed to [k][n] fp32, with pair-swizzle baked into each 256-float slice
__device__ float g_Ct[DD * N_CORE];     // 25.2 MB

__device__ float g_c2[N_CORE];
__device__ float g_e2[M_ROWS];
__device__ float g_minval[NSPLIT][M_ROWS];
__device__ int   g_argmin[NSPLIT][M_ROWS];
__device__ float g_score[M_ROWS];
__device__ int   g_loc[M_ROWS];
__device__ float g_bscore[BSZ];
__device__ int   g_bpatch[BSZ];
__device__ int   g_bnn[BSZ];
__device__ int   g_support[BSZ][NK];

__device__ __forceinline__ float finf() { return __int_as_float(0x7f800000); }

__device__ __forceinline__ uint32_t smem_u32(const void* p) {
    uint32_t a;
    asm("{ .reg .u64 t; cvta.to.shared.u64 t, %1; cvt.u32.u64 %0, t; }" : "=r"(a) : "l"(p));
    return a;
}
__device__ __forceinline__ void cpa16(uint32_t dst, const void* src) {
    asm volatile("cp.async.ca.shared.global [%0], [%1], 16;" :: "r"(dst), "l"(src));
}
__device__ __forceinline__ unsigned long long lds64(uint32_t a) {
    unsigned long long v;
    asm volatile("ld.shared.b64 %0, [%1];" : "=l"(v) : "r"(a));
    return v;
}
__device__ __forceinline__ float lds32f(uint32_t a) {
    float v;
    asm volatile("ld.shared.f32 %0, [%1];" : "=f"(v) : "r"(a));
    return v;
}
// packed f32x2 (sm_100-family base ISA)
__device__ __forceinline__ void ffma2(unsigned long long& d, unsigned long long a,
                                      unsigned long long b) {
    asm volatile("fma.rn.f32x2 %0, %1, %2, %0;" : "+l"(d) : "l"(a), "l"(b));
}
__device__ __forceinline__ unsigned long long dup2(float x) {
    unsigned long long r;
    asm("mov.b64 %0, {%1, %1};" : "=l"(r) : "f"(x));
    return r;
}
__device__ __forceinline__ void unpack2(float& lo, float& hi, unsigned long long v) {
    asm("mov.b64 {%0, %1}, %2;" : "=f"(lo), "=f"(hi) : "l"(v));
}

// ---------------- pad kernel (keeps mindist in the ncu capture slot) ----------------
__global__ void pad_kernel() {}

// ---------------- squared norms ----------------
__global__ void norms_kernel(const float* __restrict__ X, int which) {
    int row = blockIdx.x;
    const float4* x = reinterpret_cast<const float4*>(X + (size_t)row * DD);
    float s = 0.f;
    for (int i = threadIdx.x; i < DD / 4; i += blockDim.x) {
        float4 v = __ldg(&x[i]);
        s += v.x * v.x + v.y * v.y + v.z * v.z + v.w * v.w;
    }
#pragma unroll
    for (int o = 16; o > 0; o >>= 1) s += __shfl_down_sync(0xffffffffu, s, o);
    __shared__ float ws[4];
    int lane = threadIdx.x & 31, wid = threadIdx.x >> 5;
    if (lane == 0) ws[wid] = s;
    __syncthreads();
    if (threadIdx.x == 0) {
        float tot = ws[0] + ws[1] + ws[2] + ws[3];
        if (which) g_e2[row] = tot; else g_c2[row] = tot;
    }
}

// ---------------- transpose C -> g_Ct[k][n] with per-slice pair swizzle ----------------
// grid (64 slices, 12 kchunks), 256 threads. Pair pi (2 floats) of slice stored at
// physical pair pi ^ ((pi>>4)&7), matching the compute kernel's conflict-free loads.
__global__ void transposeC_kernel(const float* __restrict__ C) {
    __shared__ float tile[256][33];
    int s = blockIdx.x, kc = blockIdx.y;
    int tid = threadIdx.x;
    const float4* src = reinterpret_cast<const float4*>(
        C + (size_t)(s * 256 + tid) * DD + kc * BK);
#pragma unroll
    for (int u = 0; u < 8; u++) {
        float4 v = __ldg(&src[u]);
        tile[tid][u * 4 + 0] = v.x;
        tile[tid][u * 4 + 1] = v.y;
        tile[tid][u * 4 + 2] = v.z;
        tile[tid][u * 4 + 3] = v.w;
    }
    __syncthreads();
    int k = tid >> 3, sub = tid & 7;
    float* dst = g_Ct + (size_t)(kc * BK + k) * N_CORE + s * 256;
#pragma unroll
    for (int j = 0; j < 16; j++) {
        int pi = sub * 16 + j;
        int phys = pi ^ ((pi >> 4) & 7);
        float2 v = make_float2(tile[2 * pi][k], tile[2 * pi + 1][k]);
        *reinterpret_cast<float2*>(dst + phys * 2) = v;
    }
}

// ---------------- main: exact fp32 min-distance, FFMA2, fully pipelined ----------------
// grid (49, 3), 256 threads (16 tx x 16 ty), CTA tile 128x256, thread tile 8m x 16n.
// A: cp.async [2][128][32]f row-major (broadcast LDS.32 loads).
// B: cp.async verbatim from pre-transposed+pre-swizzled g_Ct -> conflict-free LDS.64.
// Inner loop register-double-buffers bd[8] and ad[8]: loads for k+1 issue before the
// 64 FFMA2 of k, so the FMA block never waits on shared memory.
// Exact fp32 -> strict '<' + ascending n = first-occurrence argmin (matches jnp.argmin).
__global__ void __launch_bounds__(256, 1) mindist_kernel(const float* __restrict__ E) {
    extern __shared__ float sm[];
    uint32_t sb = smem_u32(sm);
    int tid = threadIdx.x;
    int tx = tid & 15, ty = tid >> 4;
    int xmask = (tx >> 1) & 7;
    int mb = blockIdx.x, gy = blockIdx.y;
    int m0 = mb * BM;
    int ts = (NT_ALL * gy) / NSPLIT;
    int te = (NT_ALL * (gy + 1)) / NSPLIT;

    // staging addresses
    const float* eSrc = E + (size_t)(m0 + (tid >> 1)) * DD + (tid & 1) * 16;
    uint32_t aDst = sb + (uint32_t)(tid >> 1) * 128 + (tid & 1) * 64;
    const float* bSrcBase = g_Ct + (size_t)(tid >> 3) * N_CORE + (tid & 7) * 4;
    uint32_t bDst = sb + OFF_B + (uint32_t)(tid >> 3) * 1024 + (tid & 7) * 16;

    // compute-side bases
    uint32_t aLd = sb + (uint32_t)ty * 1024;            // + st*16384 + i*128 + k*4
    uint32_t bLd = sb + OFF_B + (uint32_t)tx * 64;      // + st*32768 + k*1024 + (p^xmask)*8

    unsigned long long acc[64];
#pragma unroll
    for (int i = 0; i < 64; i++) acc[i] = 0ull;

    float rmin[8]; int ridx[8];
#pragma unroll
    for (int i = 0; i < 8; i++) { rmin[i] = finf(); ridx[i] = 0x7fffffff; }

    auto issue_stage = [&](int st_, int t_, int kc_) {
        uint32_t ad = aDst + st_ * 16384;
        const float* as = eSrc + kc_ * BK;
#pragma unroll
        for (int j = 0; j < 4; j++) cpa16(ad + j * 16, as + j * 4);
        uint32_t bd = bDst + st_ * 32768;
        const float* bs = bSrcBase + (size_t)kc_ * BK * N_CORE + t_ * 256;
#pragma unroll
        for (int j = 0; j < 8; j++) cpa16(bd + j * 128, bs + j * 32);
        asm volatile("cp.async.commit_group;" ::: "memory");
    };

    issue_stage(0, ts, 0);

    for (int t = ts; t < te; t++) {
#pragma unroll 1
        for (int kc = 0; kc < KCHUNKS; kc++) {
            int st = ((t - ts) * KCHUNKS + kc) & 1;
            bool has_next = !(t == te - 1 && kc == KCHUNKS - 1);
            if (has_next) {
                int nkc = kc + 1, nt = t;
                if (nkc == KCHUNKS) { nkc = 0; nt = t + 1; }
                issue_stage(st ^ 1, nt, nkc);
                asm volatile("cp.async.wait_group 1;" ::: "memory");
            } else {
                asm volatile("cp.async.wait_group 0;" ::: "memory");
            }
            __syncthreads();

            uint32_t aB = aLd + st * 16384;
            uint32_t bB = bLd + st * 32768;

            unsigned long long bdb[2][8], adb[2][8];
#pragma unroll
            for (int p = 0; p < 8; p++) bdb[0][p] = lds64(bB + ((p ^ xmask) * 8));
#pragma unroll
            for (int i = 0; i < 8; i++) adb[0][i] = dup2(lds32f(aB + i * 128));

#pragma unroll 4
            for (int k = 0; k < BK; k++) {
                int cur = k & 1, nxt = cur ^ 1;
                if (k < BK - 1) {
#pragma unroll
                    for (int p = 0; p < 8; p++)
                        bdb[nxt][p] = lds64(bB + (k + 1) * 1024 + ((p ^ xmask) * 8));
#pragma unroll
                    for (int i = 0; i < 8; i++)
                        adb[nxt][i] = dup2(lds32f(aB + i * 128 + (k + 1) * 4));
                }
#pragma unroll
                for (int i = 0; i < 8; i++)
#pragma unroll
                    for (int p = 0; p < 8; p++)
                        ffma2(acc[i * 8 + p], adb[cur][i], bdb[cur][p]);
            }
            __syncthreads();
        }

        // epilogue: dd = c2[n] - 2*dot, running (min, argmin); n ascending per slot
#pragma unroll
        for (int p = 0; p < 8; p++) {
            int n = t * BN + tx * 16 + 2 * p;
            float2 c2v = __ldg(reinterpret_cast<const float2*>(g_c2 + n));
#pragma unroll
            for (int i = 0; i < 8; i++) {
                float lo, hi;
                unpack2(lo, hi, acc[i * 8 + p]);
                float dd = fmaf(-2.f, lo, c2v.x);
                if (dd < rmin[i]) { rmin[i] = dd; ridx[i] = n; }
                dd = fmaf(-2.f, hi, c2v.y);
                if (dd < rmin[i]) { rmin[i] = dd; ridx[i] = n + 1; }
                acc[i * 8 + p] = 0ull;
            }
        }
    }

    // cross-thread (tx) reduction, lexicographic (val, idx); overlay smem
    __syncthreads();
    float* sval = sm;                                    // [128][16]
    int*   sidx = reinterpret_cast<int*>(sm + 2048);     // [128][16]
#pragma unroll
    for (int i = 0; i < 8; i++) {
        sval[(ty * 8 + i) * 16 + tx] = rmin[i];
        sidx[(ty * 8 + i) * 16 + tx] = ridx[i];
    }
    __syncthreads();
    if (tid < BM) {
        float bv = sval[tid * 16]; int bi = sidx[tid * 16];
#pragma unroll
        for (int u = 1; u < 16; u++) {
            float v = sval[tid * 16 + u]; int id = sidx[tid * 16 + u];
            if (v < bv || (v == bv && id < bi)) { bv = v; bi = id; }
        }
        g_minval[gy][m0 + tid] = bv;
        g_argmin[gy][m0 + tid] = bi;
    }
}

// ---------------- combine splits + score = sqrt(e2 + minval) ----------------
__global__ void score_kernel() {
    int m = blockIdx.x * 256 + threadIdx.x;
    if (m >= M_ROWS) return;
    float bv = g_minval[0][m]; int bi = g_argmin[0][m];
#pragma unroll
    for (int s = 1; s < NSPLIT; s++) {
        float v = g_minval[s][m]; int id = g_argmin[s][m];
        if (v < bv || (v == bv && id < bi)) { bv = v; bi = id; }
    }
    g_score[m] = sqrtf(fmaxf(g_e2[m] + bv, 0.f));
    g_loc[m] = bi;
}

// ---------------- per-batch argmax over P patches ----------------
__global__ void bargmax_kernel() {
    int b = blockIdx.x;
    int tid = threadIdx.x;
    float bv = -finf(); int bi = 0x7fffffff;
    for (int p = tid; p < PP; p += 256) {
        float v = g_score[b * PP + p];
        if (v > bv) { bv = v; bi = p; }   // strict > keeps first occurrence
    }
    __shared__ float sv[256]; __shared__ int si[256];
    sv[tid] = bv; si[tid] = bi;
    __syncthreads();
    for (int s = 128; s > 0; s >>= 1) {
        if (tid < s) {
            if (sv[tid + s] > sv[tid] ||
                (sv[tid + s] == sv[tid] && si[tid + s] < si[tid])) {
                sv[tid] = sv[tid + s]; si[tid] = si[tid + s];
            }
        }
        __syncthreads();
    }
    if (tid == 0) {
        g_bscore[b] = sv[0];
        g_bpatch[b] = si[0];
        g_bnn[b]    = g_loc[b * PP + si[0]];
    }
}

// ---------------- k-NN of nn_sample within coreset (top-9 smallest) ----------------
__global__ void knn_kernel(const float* __restrict__ C) {
    int b = blockIdx.x;
    int tid = threadIdx.x;
    __shared__ float nns[DD];
    __shared__ float cv[256 * NK];
    __shared__ int   ci[256 * NK];
    __shared__ float sv[256];
    __shared__ int   si[256];
    int nn = g_bnn[b];
    for (int k = tid; k < DD; k += 256) nns[k] = __ldg(&C[(size_t)nn * DD + k]);
    __syncthreads();
    float c2nn = g_c2[nn];

    float tv[NK]; int ti[NK];
#pragma unroll
    for (int q = 0; q < NK; q++) { tv[q] = finf(); ti[q] = 0x7fffffff; }

    for (int n = tid; n < N_CORE; n += 256) {
        const float4* cr = reinterpret_cast<const float4*>(&C[(size_t)n * DD]);
        float dot = 0.f;
#pragma unroll 8
        for (int i = 0; i < DD / 4; i++) {
            float4 v = __ldg(&cr[i]);
            float4 u = *reinterpret_cast<const float4*>(&nns[i * 4]);
            dot = fmaf(v.x, u.x, dot);
            dot = fmaf(v.y, u.y, dot);
            dot = fmaf(v.z, u.z, dot);
            dot = fmaf(v.w, u.w, dot);
        }
        float dd = c2nn + g_c2[n] - 2.f * dot;   // sqrt monotonic -> compare d^2
        if (dd < tv[NK - 1]) {
            tv[NK - 1] = dd; ti[NK - 1] = n;
#pragma unroll
            for (int q = NK - 1; q > 0; q--) {
                if (tv[q] < tv[q - 1]) {
                    float a = tv[q]; tv[q] = tv[q - 1]; tv[q - 1] = a;
                    int   c = ti[q]; ti[q] = ti[q - 1]; ti[q - 1] = c;
                }
            }
        }
    }
#pragma unroll
    for (int q = 0; q < NK; q++) { cv[tid * NK + q] = tv[q]; ci[tid * NK + q] = ti[q]; }
    __syncthreads();

    for (int it = 0; it < NK; it++) {
        float bv = finf(); int bi = 0x7fffffff;
#pragma unroll
        for (int q = 0; q < NK; q++) {
            float v = cv[tid * NK + q]; int id = ci[tid * NK + q];
            if (v < bv || (v == bv && id < bi)) { bv = v; bi = id; }
        }
        sv[tid] = bv; si[tid] = bi;
        __syncthreads();
        for (int s = 128; s > 0; s >>= 1) {
            if (tid < s) {
                if (sv[tid + s] < sv[tid] ||
                    (sv[tid + s] == sv[tid] && si[tid + s] < si[tid])) {
                    sv[tid] = sv[tid + s]; si[tid] = si[tid + s];
                }
            }
            __syncthreads();
        }
        int wi = si[0];
        if (tid == 0) g_support[b][it] = wi;
        __syncthreads();
#pragma unroll
        for (int q = 0; q < NK; q++)
            if (ci[tid * NK + q] == wi) cv[tid * NK + q] = finf();
        __syncthreads();
    }
}

// ---------------- final: d_sup, softmax, output ----------------
__global__ void final_kernel(const float* __restrict__ E, const float* __restrict__ C,
                             float* __restrict__ out) {
    int b = blockIdx.x;
    int tid = threadIdx.x;  // 128 threads
    __shared__ float qf[DD];
    __shared__ float dsup[NK];
    __shared__ float red[128];
    int m = b * PP + g_bpatch[b];
    for (int k = tid; k < DD; k += 128) qf[k] = __ldg(&E[(size_t)m * DD + k]);
    __syncthreads();
    float q2 = g_e2[m];
    for (int kk = 0; kk < NK; kk++) {
        int s = g_support[b][kk];
        float dot = 0.f;
        for (int k = tid; k < DD; k += 128)
            dot = fmaf(qf[k], __ldg(&C[(size_t)s * DD + k]), dot);
        red[tid] = dot;
        __syncthreads();
        for (int st = 64; st > 0; st >>= 1) {
            if (tid < st) red[tid] += red[tid + st];
            __syncthreads();
        }
        if (tid == 0) dsup[kk] = sqrtf(fmaxf(q2 + g_c2[s] - 2.f * red[0], 0.f));
        __syncthreads();
    }
    if (tid == 0) {
        float mx = dsup[0];
#pragma unroll
        for (int k = 1; k < NK; k++) mx = fmaxf(mx, dsup[k]);
        float se = 0.f, e0 = 0.f;
#pragma unroll
        for (int k = 0; k < NK; k++) {
            float e = expf(dsup[k] - mx);
            if (k == 0) e0 = e;
            se += e;
        }
        out[b] = (1.f - e0 / se) * g_bscore[b];
    }
}

// ---------------- launcher ----------------
extern "C" void kernel_launch(void* const* d_in, const int* in_sizes, int n_in,
                              void* d_out, int out_size) {
    const float* E = (const float*)d_in[0];   // [6272, 384]
    const float* C = (const float*)d_in[1];   // [16384, 384]
    float* out = (float*)d_out;               // [8]
    (void)in_sizes; (void)n_in; (void)out_size;

    cudaFuncSetAttribute(mindist_kernel,
                         cudaFuncAttributeMaxDynamicSharedMemorySize, SMEM_TOTAL);

    norms_kernel<<<N_CORE, 128>>>(C, 0);
    norms_kernel<<<M_ROWS, 128>>>(E, 1);
    transposeC_kernel<<<dim3(N_CORE / 256, KCHUNKS), 256>>>(C);
    pad_kernel<<<1, 32>>>();                      // keeps mindist in ncu capture slot
    mindist_kernel<<<dim3(MBLKS, NSPLIT), 256, SMEM_TOTAL>>>(E);
    score_kernel<<<(M_ROWS + 255) / 256, 256>>>();
    bargmax_kernel<<<BSZ, 256>>>();
    knn_kernel<<<BSZ, 256>>>(C);
    final_kernel<<<BSZ, 128>>>(E, C, out);
}

// round 16
// speedup vs baseline: 1.5531x; 1.5531x over previous
#include <cuda_runtime.h>
#include <cstdint>
#include <cstdio>

// Problem constants: B=8, P=784, D=384, N=16384
#define DD      384
#define M_ROWS  6272
#define N_CORE  16384
#define BSZ     8
#define PP      784
#define NK      9

#define NSPLIT  3
#define BM      128
#define BN      256
#define BKT     32
#define KCHUNKS (DD / BKT)              // 12
#define NT_ALL  (N_CORE / BN)           // 64
#define MBLKS   (M_ROWS / BM)           // 49

// smem (floats padded so bank = 8c+g, a perfect permutation -> conflict-free)
#define APAD    136
#define BPAD    264
#define A_BUF   (BKT * APAD * 4)        // 17408 B
#define B_BUF   (BKT * BPAD * 4)        // 33792 B
#define OFF_B2  (2 * A_BUF)             // 34816
#define SMEM_T  (2 * A_BUF + 2 * B_BUF) // 102400

// ---------------- device scratch (no allocations allowed) ----------------
__device__ float g_Et[DD * M_ROWS];     // tf32-rounded E, transposed [k][m]
__device__ float g_Ct[DD * N_CORE];     // tf32-rounded C, transposed [k][n]

__device__ float g_c2[N_CORE];
__device__ float g_e2[M_ROWS];
__device__ float g_cand_val[NSPLIT][M_ROWS][8];
__device__ int   g_cand_idx[NSPLIT][M_ROWS][8];
__device__ float g_score[M_ROWS];
__device__ int   g_loc[M_ROWS];
__device__ float g_bscore[BSZ];
__device__ int   g_bpatch[BSZ];
__device__ int   g_bnn[BSZ];
__device__ int   g_support[BSZ][NK];

__device__ __forceinline__ float finf() { return __int_as_float(0x7f800000); }

__device__ __forceinline__ uint32_t smem_u32(const void* p) {
    uint32_t a;
    asm("{ .reg .u64 t; cvta.to.shared.u64 t, %1; cvt.u32.u64 %0, t; }" : "=r"(a) : "l"(p));
    return a;
}
__device__ __forceinline__ void cpa16(uint32_t dst, const void* src) {
    asm volatile("cp.async.ca.shared.global [%0], [%1], 16;" :: "r"(dst), "l"(src));
}
__device__ __forceinline__ uint32_t lds32u(uint32_t a) {
    uint32_t v;
    asm volatile("ld.shared.b32 %0, [%1];" : "=r"(v) : "r"(a));
    return v;
}
__device__ __forceinline__ float tf32r(float x) {
    uint32_t u;
    asm("cvt.rna.tf32.f32 %0, %1;" : "=r"(u) : "f"(x));
    return __uint_as_float(u);
}
// m16n8k8 tf32 mma, fp32 accumulate in place
__device__ __forceinline__ void mma_tf32(float* d, const uint32_t* a, const uint32_t* b) {
    asm volatile("mma.sync.aligned.m16n8k8.row.col.f32.tf32.tf32.f32 "
                 "{%0,%1,%2,%3}, {%4,%5,%6,%7}, {%8,%9}, {%0,%1,%2,%3};"
                 : "+f"(d[0]), "+f"(d[1]), "+f"(d[2]), "+f"(d[3])
                 : "r"(a[0]), "r"(a[1]), "r"(a[2]), "r"(a[3]), "r"(b[0]), "r"(b[1]));
}

// ---------------- squared norms ----------------
__global__ void norms_kernel(const float* __restrict__ X, int which) {
    int row = blockIdx.x;
    const float4* x = reinterpret_cast<const float4*>(X + (size_t)row * DD);
    float s = 0.f;
    for (int i = threadIdx.x; i < DD / 4; i += blockDim.x) {
        float4 v = __ldg(&x[i]);
        s += v.x * v.x + v.y * v.y + v.z * v.z + v.w * v.w;
    }
#pragma unroll
    for (int o = 16; o > 0; o >>= 1) s += __shfl_down_sync(0xffffffffu, s, o);
    __shared__ float ws[4];
    int lane = threadIdx.x & 31, wid = threadIdx.x >> 5;
    if (lane == 0) ws[wid] = s;
    __syncthreads();
    if (threadIdx.x == 0) {
        float tot = ws[0] + ws[1] + ws[2] + ws[3];
        if (which) g_e2[row] = tot; else g_c2[row] = tot;
    }
}

// ---------------- prep: tf32-round + transpose E and C into [k][row] ----------------
__global__ void prep_kernel(const float* __restrict__ E, const float* __restrict__ C) {
    int idx = blockIdx.x * 256 + threadIdx.x;
    const int eq = M_ROWS * 96;
    if (idx < eq) {
        int row = idx / 96, q = idx % 96;
        float4 v = __ldg(reinterpret_cast<const float4*>(E + (size_t)row * DD + q * 4));
        g_Et[(size_t)(q * 4 + 0) * M_ROWS + row] = tf32r(v.x);
        g_Et[(size_t)(q * 4 + 1) * M_ROWS + row] = tf32r(v.y);
        g_Et[(size_t)(q * 4 + 2) * M_ROWS + row] = tf32r(v.z);
        g_Et[(size_t)(q * 4 + 3) * M_ROWS + row] = tf32r(v.w);
    } else if (idx < eq + N_CORE * 96) {
        idx -= eq;
        int row = idx / 96, q = idx % 96;
        float4 v = __ldg(reinterpret_cast<const float4*>(C + (size_t)row * DD + q * 4));
        g_Ct[(size_t)(q * 4 + 0) * N_CORE + row] = tf32r(v.x);
        g_Ct[(size_t)(q * 4 + 1) * N_CORE + row] = tf32r(v.y);
        g_Ct[(size_t)(q * 4 + 2) * N_CORE + row] = tf32r(v.z);
        g_Ct[(size_t)(q * 4 + 3) * N_CORE + row] = tf32r(v.w);
    }
}

// ---------------- main: tf32 mma candidate-pruning min-GEMM ----------------
// grid (49, 3), 256 threads = 8 warps (wm 2 x wn 4), CTA tile 128x256, warp tile 64x64.
// m16n8k8 fragments (PTX ISA, g = lane>>2, c = lane&3):
//   A (16x8 row-major): a0=(g,c) a1=(g+8,c) a2=(g,c+4) a3=(g+8,c+4)
//   B (8x8,  col output): b0=(k=c, n=g) b1=(k=c+4, n=g)
//   D (16x8 f32): d0=(g,2c) d1=(g,2c+1) d2=(g+8,2c) d3=(g+8,2c+1)
// Per (row, gy, 64-col region) keep approximate top-2 -> exact fp32 rescore after.
__global__ void __launch_bounds__(256, 1) mindist_tc_kernel() {
    extern __shared__ float sm[];
    uint32_t sb = smem_u32(sm);
    int tid = threadIdx.x;
    int lane = tid & 31, warp = tid >> 5;
    int g = lane >> 2, c = lane & 3;
    int wm = warp >> 2, wn = warp & 3;
    int mb = blockIdx.x, gy = blockIdx.y;
    int m0 = mb * BM;
    int ts = (NT_ALL * gy) / NSPLIT;
    int te = (NT_ALL * (gy + 1)) / NSPLIT;

    // fragment base addresses (k and subtile offsets added in-loop)
    uint32_t aB0 = sb + (uint32_t)(c * APAD + wm * 64 + g) * 4;
    uint32_t bB0 = sb + OFF_B2 + (uint32_t)(c * BPAD + wn * 64 + g) * 4;

    auto issue_stage = [&](int st_, int t_, int kc_) {
        // A: 32 k-rows x 128 floats = 1024 float4, 4 per thread
#pragma unroll
        for (int u = 0; u < 4; u++) {
            int idx = u * 256 + tid;
            int kr = idx >> 5, pos = idx & 31;
            cpa16(sb + st_ * A_BUF + (uint32_t)(kr * APAD + pos * 4) * 4,
                  g_Et + (size_t)(kc_ * BKT + kr) * M_ROWS + m0 + pos * 4);
        }
        // B: 32 k-rows x 256 floats = 2048 float4, 8 per thread
#pragma unroll
        for (int u = 0; u < 8; u++) {
            int idx = u * 256 + tid;
            int kr = idx >> 6, pos = idx & 63;
            cpa16(sb + OFF_B2 + st_ * B_BUF + (uint32_t)(kr * BPAD + pos * 4) * 4,
                  g_Ct + (size_t)(kc_ * BKT + kr) * N_CORE + t_ * 256 + pos * 4);
        }
        asm volatile("cp.async.commit_group;" ::: "memory");
    };

    float acc[4][8][4];
#pragma unroll
    for (int mt = 0; mt < 4; mt++)
#pragma unroll
        for (int jn = 0; jn < 8; jn++)
#pragma unroll
            for (int q = 0; q < 4; q++) acc[mt][jn][q] = 0.f;

    // per-thread top-2 per row-slot (8 slots: mt x {g, g+8})
    float v1[8], v2[8]; int i1[8], i2[8];
#pragma unroll
    for (int s = 0; s < 8; s++) { v1[s] = finf(); v2[s] = finf(); i1[s] = 0x7fffffff; i2[s] = 0x7fffffff; }

    issue_stage(0, ts, 0);

    for (int t = ts; t < te; t++) {
#pragma unroll 1
        for (int kc = 0; kc < KCHUNKS; kc++) {
            int st = ((t - ts) * KCHUNKS + kc) & 1;
            bool has_next = !(t == te - 1 && kc == KCHUNKS - 1);
            if (has_next) {
                int nkc = kc + 1, nt = t;
                if (nkc == KCHUNKS) { nkc = 0; nt = t + 1; }
                issue_stage(st ^ 1, nt, nkc);
                asm volatile("cp.async.wait_group 1;" ::: "memory");
            } else {
                asm volatile("cp.async.wait_group 0;" ::: "memory");
            }
            __syncthreads();

            uint32_t aB = aB0 + st * A_BUF;
            uint32_t bB = bB0 + st * B_BUF;
#pragma unroll
            for (int ks = 0; ks < 4; ks++) {
                uint32_t kofA = (uint32_t)(ks * 8 * APAD) * 4;
                uint32_t kofB = (uint32_t)(ks * 8 * BPAD) * 4;
                uint32_t bf[8][2];
#pragma unroll
                for (int jn = 0; jn < 8; jn++) {
                    bf[jn][0] = lds32u(bB + kofB + (uint32_t)(jn * 8) * 4);
                    bf[jn][1] = lds32u(bB + kofB + (uint32_t)(4 * BPAD + jn * 8) * 4);
                }
#pragma unroll
                for (int mt = 0; mt < 4; mt++) {
                    uint32_t af[4];
                    uint32_t a0 = aB + kofA + (uint32_t)(mt * 16) * 4;
                    af[0] = lds32u(a0);
                    af[1] = lds32u(a0 + 32);                       // row +8
                    af[2] = lds32u(a0 + (uint32_t)(4 * APAD) * 4); // k +4
                    af[3] = lds32u(a0 + (uint32_t)(4 * APAD) * 4 + 32);
#pragma unroll
                    for (int jn = 0; jn < 8; jn++)
                        mma_tf32(acc[mt][jn], af, bf[jn]);
                }
            }
            __syncthreads();
        }

        // epilogue: dd = c2[n] - 2*dot; streaming top-2 per slot (n ascending ->
        // strict lexicographic keeps first occurrence, matching jnp.argmin)
#pragma unroll
        for (int jn = 0; jn < 8; jn++) {
            int n = t * BN + wn * 64 + jn * 8 + 2 * c;
            float2 c2v = __ldg(reinterpret_cast<const float2*>(g_c2 + n));
#pragma unroll
            for (int mt = 0; mt < 4; mt++) {
                float* d = acc[mt][jn];
#pragma unroll
                for (int q = 0; q < 4; q++) {
                    int s = 2 * mt + (q >> 1);          // d0,d1 -> row g; d2,d3 -> row g+8
                    int nn = n + (q & 1);
                    float dd = fmaf(-2.f, d[q], (q & 1) ? c2v.y : c2v.x);
                    if (dd < v2[s] || (dd == v2[s] && nn < i2[s])) {
                        v2[s] = dd; i2[s] = nn;
                        if (v2[s] < v1[s] || (v2[s] == v1[s] && i2[s] < i1[s])) {
                            float tv = v1[s]; v1[s] = v2[s]; v2[s] = tv;
                            int   ti = i1[s]; i1[s] = i2[s]; i2[s] = ti;
                        }
                    }
                    d[q] = 0.f;
                }
            }
        }
    }

    // quad merge (lanes 4g..4g+3 share rows, own disjoint n) -> region top-2
#pragma unroll
    for (int s = 0; s < 8; s++) {
#pragma unroll
        for (int off = 1; off <= 2; off <<= 1) {
            float ov1 = __shfl_xor_sync(0xffffffffu, v1[s], off);
            int   oi1 = __shfl_xor_sync(0xffffffffu, i1[s], off);
            float ov2 = __shfl_xor_sync(0xffffffffu, v2[s], off);
            int   oi2 = __shfl_xor_sync(0xffffffffu, i2[s], off);
            bool ofirst = (ov1 < v1[s]) || (ov1 == v1[s] && oi1 < i1[s]);
            float nv1, nv2; int ni1, ni2;
            if (ofirst) {
                nv1 = ov1; ni1 = oi1;
                if (v1[s] < ov2 || (v1[s] == ov2 && i1[s] < oi2)) { nv2 = v1[s]; ni2 = i1[s]; }
                else                                               { nv2 = ov2;  ni2 = oi2;  }
            } else {
                nv1 = v1[s]; ni1 = i1[s];
                if (ov1 < v2[s] || (ov1 == v2[s] && oi1 < i2[s])) { nv2 = ov1;  ni2 = oi1;  }
                else                                               { nv2 = v2[s]; ni2 = i2[s]; }
            }
            v1[s] = nv1; i1[s] = ni1; v2[s] = nv2; i2[s] = ni2;
        }
        if (c == 0) {
            int row = m0 + wm * 64 + (s >> 1) * 16 + (s & 1) * 8 + g;
            g_cand_val[gy][row][wn * 2]     = v1[s];
            g_cand_idx[gy][row][wn * 2]     = i1[s];
            g_cand_val[gy][row][wn * 2 + 1] = v2[s];
            g_cand_idx[gy][row][wn * 2 + 1] = i2[s];
        }
    }
}

// ---------------- exact fp32 rescore of the 24 candidates per row ----------------
__global__ void rescore_kernel(const float* __restrict__ E, const float* __restrict__ C) {
    int r = blockIdx.x * 8 + (threadIdx.x >> 5);
    if (r >= M_ROWS) return;
    int lane = threadIdx.x & 31;
    float e[12];
#pragma unroll
    for (int i = 0; i < 12; i++) e[i] = __ldg(&E[(size_t)r * DD + lane + 32 * i]);
    float bv = finf(); int bi = 0x7fffffff;
#pragma unroll 1
    for (int cc = 0; cc < 3 * 8; cc++) {
        int n = g_cand_idx[cc >> 3][r][cc & 7];
        const float* cr = C + (size_t)n * DD;
        float dot = 0.f;
#pragma unroll
        for (int i = 0; i < 12; i++) dot = fmaf(e[i], __ldg(&cr[lane + 32 * i]), dot);
#pragma unroll
        for (int o = 16; o > 0; o >>= 1) dot += __shfl_xor_sync(0xffffffffu, dot, o);
        float dd = fmaf(-2.f, dot, __ldg(&g_c2[n]));
        if (dd < bv || (dd == bv && n < bi)) { bv = dd; bi = n; }
    }
    if (lane == 0) {
        g_score[r] = sqrtf(fmaxf(g_e2[r] + bv, 0.f));
        g_loc[r] = bi;
    }
}

// ---------------- per-batch argmax over P patches ----------------
__global__ void bargmax_kernel() {
    int b = blockIdx.x;
    int tid = threadIdx.x;
    float bv = -finf(); int bi = 0x7fffffff;
    for (int p = tid; p < PP; p += 256) {
        float v = g_score[b * PP + p];
        if (v > bv) { bv = v; bi = p; }   // strict > keeps first occurrence
    }
    __shared__ float sv[256]; __shared__ int si[256];
    sv[tid] = bv; si[tid] = bi;
    __syncthreads();
    for (int s = 128; s > 0; s >>= 1) {
        if (tid < s) {
            if (sv[tid + s] > sv[tid] ||
                (sv[tid + s] == sv[tid] && si[tid + s] < si[tid])) {
                sv[tid] = sv[tid + s]; si[tid] = si[tid + s];
            }
        }
        __syncthreads();
    }
    if (tid == 0) {
        g_bscore[b] = sv[0];
        g_bpatch[b] = si[0];
        g_bnn[b]    = g_loc[b * PP + si[0]];
    }
}

// ---------------- k-NN of nn_sample within coreset (top-9 smallest) ----------------
__global__ void knn_kernel(const float* __restrict__ C) {
    int b = blockIdx.x;
    int tid = threadIdx.x;
    __shared__ float nns[DD];
    __shared__ float cv[256 * NK];
    __shared__ int   ci[256 * NK];
    __shared__ float sv[256];
    __shared__ int   si[256];
    int nn = g_bnn[b];
    for (int k = tid; k < DD; k += 256) nns[k] = __ldg(&C[(size_t)nn * DD + k]);
    __syncthreads();
    float c2nn = g_c2[nn];

    float tv[NK]; int ti[NK];
#pragma unroll
    for (int q = 0; q < NK; q++) { tv[q] = finf(); ti[q] = 0x7fffffff; }

    for (int n = tid; n < N_CORE; n += 256) {
        const float4* cr = reinterpret_cast<const float4*>(&C[(size_t)n * DD]);
        float dot = 0.f;
#pragma unroll 8
        for (int i = 0; i < DD / 4; i++) {
            float4 v = __ldg(&cr[i]);
            float4 u = *reinterpret_cast<const float4*>(&nns[i * 4]);
            dot = fmaf(v.x, u.x, dot);
            dot = fmaf(v.y, u.y, dot);
            dot = fmaf(v.z, u.z, dot);
            dot = fmaf(v.w, u.w, dot);
        }
        float dd = c2nn + g_c2[n] - 2.f * dot;   // sqrt monotonic -> compare d^2
        if (dd < tv[NK - 1]) {
            tv[NK - 1] = dd; ti[NK - 1] = n;
#pragma unroll
            for (int q = NK - 1; q > 0; q--) {
                if (tv[q] < tv[q - 1]) {
                    float a = tv[q]; tv[q] = tv[q - 1]; tv[q - 1] = a;
                    int   c = ti[q]; ti[q] = ti[q - 1]; ti[q - 1] = c;
                }
            }
        }
    }
#pragma unroll
    for (int q = 0; q < NK; q++) { cv[tid * NK + q] = tv[q]; ci[tid * NK + q] = ti[q]; }
    __syncthreads();

    for (int it = 0; it < NK; it++) {
        float bv = finf(); int bi = 0x7fffffff;
#pragma unroll
        for (int q = 0; q < NK; q++) {
            float v = cv[tid * NK + q]; int id = ci[tid * NK + q];
            if (v < bv || (v == bv && id < bi)) { bv = v; bi = id; }
        }
        sv[tid] = bv; si[tid] = bi;
        __syncthreads();
        for (int s = 128; s > 0; s >>= 1) {
            if (tid < s) {
                if (sv[tid + s] < sv[tid] ||
                    (sv[tid + s] == sv[tid] && si[tid + s] < si[tid])) {
                    sv[tid] = sv[tid + s]; si[tid] = si[tid + s];
                }
            }
            __syncthreads();
        }
        int wi = si[0];
        if (tid == 0) g_support[b][it] = wi;
        __syncthreads();
#pragma unroll
        for (int q = 0; q < NK; q++)
            if (ci[tid * NK + q] == wi) cv[tid * NK + q] = finf();
        __syncthreads();
    }
}

// ---------------- final: d_sup, softmax, output ----------------
__global__ void final_kernel(const float* __restrict__ E, const float* __restrict__ C,
                             float* __restrict__ out) {
    int b = blockIdx.x;
    int tid = threadIdx.x;  // 128 threads
    __shared__ float qf[DD];
    __shared__ float dsup[NK];
    __shared__ float red[128];
    int m = b * PP + g_bpatch[b];
    for (int k = tid; k < DD; k += 128) qf[k] = __ldg(&E[(size_t)m * DD + k]);
    __syncthreads();
    float q2 = g_e2[m];
    for (int kk = 0; kk < NK; kk++) {
        int s = g_support[b][kk];
        float dot = 0.f;
        for (int k = tid; k < DD; k += 128)
            dot = fmaf(qf[k], __ldg(&C[(size_t)s * DD + k]), dot);
        red[tid] = dot;
        __syncthreads();
        for (int st = 64; st > 0; st >>= 1) {
            if (tid < st) red[tid] += red[tid + st];
            __syncthreads();
        }
        if (tid == 0) dsup[kk] = sqrtf(fmaxf(q2 + g_c2[s] - 2.f * red[0], 0.f));
        __syncthreads();
    }
    if (tid == 0) {
        float mx = dsup[0];
#pragma unroll
        for (int k = 1; k < NK; k++) mx = fmaxf(mx, dsup[k]);
        float se = 0.f, e0 = 0.f;
#pragma unroll
        for (int k = 0; k < NK; k++) {
            float e = expf(dsup[k] - mx);
            if (k == 0) e0 = e;
            se += e;
        }
        out[b] = (1.f - e0 / se) * g_bscore[b];
    }
}

// ---------------- launcher ----------------
extern "C" void kernel_launch(void* const* d_in, const int* in_sizes, int n_in,
                              void* d_out, int out_size) {
    const float* E = (const float*)d_in[0];   // [6272, 384]
    const float* C = (const float*)d_in[1];   // [16384, 384]
    float* out = (float*)d_out;               // [8]
    (void)in_sizes; (void)n_in; (void)out_size;

    cudaFuncSetAttribute(mindist_tc_kernel,
                         cudaFuncAttributeMaxDynamicSharedMemorySize, SMEM_T);

    norms_kernel<<<N_CORE, 128>>>(C, 0);
    norms_kernel<<<M_ROWS, 128>>>(E, 1);
    prep_kernel<<<((M_ROWS + N_CORE) * 96 + 255) / 256, 256>>>(E, C);
    mindist_tc_kernel<<<dim3(MBLKS, NSPLIT), 256, SMEM_T>>>();   // 4th launch -> ncu slot
    rescore_kernel<<<(M_ROWS + 7) / 8, 256>>>(E, C);
    bargmax_kernel<<<BSZ, 256>>>();
    knn_kernel<<<BSZ, 256>>>(C);
    final_kernel<<<BSZ, 128>>>(E, C, out);
}

// round 17
// speedup vs baseline: 3.4344x; 2.2113x over previous
#include <cuda_runtime.h>
#include <cstdint>
#include <cstdio>

// Problem constants: B=8, P=784, D=384, N=16384
#define DD      384
#define M_ROWS  6272
#define N_CORE  16384
#define BSZ     8
#define PP      784
#define NK      9

#define NSPLIT  3
#define BM      128
#define BN      256
#define BKT     32
#define KCHUNKS (DD / BKT)              // 12
#define NT_ALL  (N_CORE / BN)           // 64
#define MBLKS   (M_ROWS / BM)           // 49
#define KNN_SLICES 16

// smem (floats padded so bank = 8c+g, a perfect permutation -> conflict-free)
#define APAD    136
#define BPAD    264
#define A_BUF   (BKT * APAD * 4)        // 17408 B
#define B_BUF   (BKT * BPAD * 4)        // 33792 B
#define OFF_B2  (2 * A_BUF)             // 34816
#define SMEM_T  (2 * A_BUF + 2 * B_BUF) // 102400

// ---------------- device scratch (no allocations allowed) ----------------
__device__ __align__(16) float g_Et[DD * M_ROWS];   // tf32-rounded E, transposed [k][m]
__device__ __align__(16) float g_Ct[DD * N_CORE];   // tf32-rounded C, transposed [k][n]

__device__ float g_c2[N_CORE];
__device__ float g_e2[M_ROWS];
__device__ float g_cand_val[NSPLIT][M_ROWS][8];
__device__ int   g_cand_idx[NSPLIT][M_ROWS][8];
__device__ float g_score[M_ROWS];
__device__ int   g_loc[M_ROWS];
__device__ float g_bscore[BSZ];
__device__ int   g_bpatch[BSZ];
__device__ int   g_bnn[BSZ];
__device__ int   g_support[BSZ][NK];
__device__ float g_pv[BSZ][KNN_SLICES][NK];
__device__ int   g_pi[BSZ][KNN_SLICES][NK];

__device__ __forceinline__ float finf() { return __int_as_float(0x7f800000); }

__device__ __forceinline__ uint32_t smem_u32(const void* p) {
    uint32_t a;
    asm("{ .reg .u64 t; cvta.to.shared.u64 t, %1; cvt.u32.u64 %0, t; }" : "=r"(a) : "l"(p));
    return a;
}
__device__ __forceinline__ void cpa16(uint32_t dst, const void* src) {
    asm volatile("cp.async.ca.shared.global [%0], [%1], 16;" :: "r"(dst), "l"(src));
}
__device__ __forceinline__ uint32_t lds32u(uint32_t a) {
    uint32_t v;
    asm volatile("ld.shared.b32 %0, [%1];" : "=r"(v) : "r"(a));
    return v;
}
__device__ __forceinline__ float tf32r(float x) {
    uint32_t u;
    asm("cvt.rna.tf32.f32 %0, %1;" : "=r"(u) : "f"(x));
    return __uint_as_float(u);
}
// m16n8k8 tf32 mma, fp32 accumulate in place
__device__ __forceinline__ void mma_tf32(float* d, const uint32_t* a, const uint32_t* b) {
    asm volatile("mma.sync.aligned.m16n8k8.row.col.f32.tf32.tf32.f32 "
                 "{%0,%1,%2,%3}, {%4,%5,%6,%7}, {%8,%9}, {%0,%1,%2,%3};"
                 : "+f"(d[0]), "+f"(d[1]), "+f"(d[2]), "+f"(d[3])
                 : "r"(a[0]), "r"(a[1]), "r"(a[2]), "r"(a[3]), "r"(b[0]), "r"(b[1]));
}

// ---------------- squared norms ----------------
__global__ void norms_kernel(const float* __restrict__ X, int which) {
    int row = blockIdx.x;
    const float4* x = reinterpret_cast<const float4*>(X + (size_t)row * DD);
    float s = 0.f;
    for (int i = threadIdx.x; i < DD / 4; i += blockDim.x) {
        float4 v = __ldg(&x[i]);
        s += v.x * v.x + v.y * v.y + v.z * v.z + v.w * v.w;
    }
#pragma unroll
    for (int o = 16; o > 0; o >>= 1) s += __shfl_down_sync(0xffffffffu, s, o);
    __shared__ float ws[4];
    int lane = threadIdx.x & 31, wid = threadIdx.x >> 5;
    if (lane == 0) ws[wid] = s;
    __syncthreads();
    if (threadIdx.x == 0) {
        float tot = ws[0] + ws[1] + ws[2] + ws[3];
        if (which) g_e2[row] = tot; else g_c2[row] = tot;
    }
}

// ---------------- prep: tf32-round + TILED transpose (coalesced writes) ----------------
// grid (64 + 25, 12): blocks [0,64) handle C, [64,89) handle E. 256 threads.
// Read phase: each thread reads one row's 32-k slice (coalesced float4 loads),
// stores tile[k][tid] (conflict-free). Write phase: thread (k, part) writes 32
// consecutive floats of output row k -> fully coalesced float4 stores.
__global__ void prep_kernel(const float* __restrict__ E, const float* __restrict__ C) {
    __shared__ float tile[32][257];
    int bx = blockIdx.x, kc = blockIdx.y;
    int tid = threadIdx.x;
    const float* src; float* dst; int nrows, row0;
    if (bx < 64) { src = C; dst = g_Ct; nrows = N_CORE; row0 = bx * 256; }
    else         { src = E; dst = g_Et; nrows = M_ROWS; row0 = (bx - 64) * 256; }

    int r = row0 + tid;
    if (r < nrows) {
        const float4* s4 = reinterpret_cast<const float4*>(src + (size_t)r * DD + kc * BKT);
#pragma unroll
        for (int u = 0; u < 8; u++) {
            float4 v = __ldg(&s4[u]);
            tile[u * 4 + 0][tid] = tf32r(v.x);
            tile[u * 4 + 1][tid] = tf32r(v.y);
            tile[u * 4 + 2][tid] = tf32r(v.z);
            tile[u * 4 + 3][tid] = tf32r(v.w);
        }
    }
    __syncthreads();

    int k = tid >> 3, part = tid & 7;
    if (row0 + part * 32 < nrows) {   // nrows is a multiple of 32
        float4* d4 = reinterpret_cast<float4*>(
            dst + (size_t)(kc * BKT + k) * nrows + row0 + part * 32);
#pragma unroll
        for (int j = 0; j < 8; j++)
            d4[j] = make_float4(tile[k][part * 32 + j * 4 + 0],
                                tile[k][part * 32 + j * 4 + 1],
                                tile[k][part * 32 + j * 4 + 2],
                                tile[k][part * 32 + j * 4 + 3]);
    }
}

// ---------------- main: tf32 mma candidate-pruning min-GEMM ----------------
// grid (49, 3), 256 threads = 8 warps (wm 2 x wn 4), CTA tile 128x256, warp tile 64x64.
// m16n8k8 fragments (PTX ISA, g = lane>>2, c = lane&3):
//   A (16x8 row-major): a0=(g,c) a1=(g+8,c) a2=(g,c+4) a3=(g+8,c+4)
//   B (8x8,  col output): b0=(k=c, n=g) b1=(k=c+4, n=g)
//   D (16x8 f32): d0=(g,2c) d1=(g,2c+1) d2=(g+8,2c) d3=(g+8,2c+1)
// A-fragment loads for mt+1 are issued before mt's mmas (register pipelining).
// Per (row, gy, 64-col region) keep approximate top-2 -> exact fp32 rescore after.
__global__ void __launch_bounds__(256, 1) mindist_tc_kernel() {
    extern __shared__ float sm[];
    uint32_t sb = smem_u32(sm);
    int tid = threadIdx.x;
    int lane = tid & 31, warp = tid >> 5;
    int g = lane >> 2, c = lane & 3;
    int wm = warp >> 2, wn = warp & 3;
    int mb = blockIdx.x, gy = blockIdx.y;
    int m0 = mb * BM;
    int ts = (NT_ALL * gy) / NSPLIT;
    int te = (NT_ALL * (gy + 1)) / NSPLIT;

    uint32_t aB0 = sb + (uint32_t)(c * APAD + wm * 64 + g) * 4;
    uint32_t bB0 = sb + OFF_B2 + (uint32_t)(c * BPAD + wn * 64 + g) * 4;

    auto issue_stage = [&](int st_, int t_, int kc_) {
#pragma unroll
        for (int u = 0; u < 4; u++) {
            int idx = u * 256 + tid;
            int kr = idx >> 5, pos = idx & 31;
            cpa16(sb + st_ * A_BUF + (uint32_t)(kr * APAD + pos * 4) * 4,
                  g_Et + (size_t)(kc_ * BKT + kr) * M_ROWS + m0 + pos * 4);
        }
#pragma unroll
        for (int u = 0; u < 8; u++) {
            int idx = u * 256 + tid;
            int kr = idx >> 6, pos = idx & 63;
            cpa16(sb + OFF_B2 + st_ * B_BUF + (uint32_t)(kr * BPAD + pos * 4) * 4,
                  g_Ct + (size_t)(kc_ * BKT + kr) * N_CORE + t_ * 256 + pos * 4);
        }
        asm volatile("cp.async.commit_group;" ::: "memory");
    };

    float acc[4][8][4];
#pragma unroll
    for (int mt = 0; mt < 4; mt++)
#pragma unroll
        for (int jn = 0; jn < 8; jn++)
#pragma unroll
            for (int q = 0; q < 4; q++) acc[mt][jn][q] = 0.f;

    float v1[8], v2[8]; int i1[8], i2[8];
#pragma unroll
    for (int s = 0; s < 8; s++) { v1[s] = finf(); v2[s] = finf(); i1[s] = 0x7fffffff; i2[s] = 0x7fffffff; }

    issue_stage(0, ts, 0);

    for (int t = ts; t < te; t++) {
#pragma unroll 1
        for (int kc = 0; kc < KCHUNKS; kc++) {
            int st = ((t - ts) * KCHUNKS + kc) & 1;
            bool has_next = !(t == te - 1 && kc == KCHUNKS - 1);
            if (has_next) {
                int nkc = kc + 1, nt = t;
                if (nkc == KCHUNKS) { nkc = 0; nt = t + 1; }
                issue_stage(st ^ 1, nt, nkc);
                asm volatile("cp.async.wait_group 1;" ::: "memory");
            } else {
                asm volatile("cp.async.wait_group 0;" ::: "memory");
            }
            __syncthreads();

            uint32_t aB = aB0 + st * A_BUF;
            uint32_t bB = bB0 + st * B_BUF;
#pragma unroll
            for (int ks = 0; ks < 4; ks++) {
                uint32_t kofA = (uint32_t)(ks * 8 * APAD) * 4;
                uint32_t kofB = (uint32_t)(ks * 8 * BPAD) * 4;
                uint32_t bf[8][2];
#pragma unroll
                for (int jn = 0; jn < 8; jn++) {
                    bf[jn][0] = lds32u(bB + kofB + (uint32_t)(jn * 8) * 4);
                    bf[jn][1] = lds32u(bB + kofB + (uint32_t)(4 * BPAD + jn * 8) * 4);
                }
                // A prefetch pipeline: load mt+1's fragments before mt's mmas
                uint32_t af[4];
                {
                    uint32_t a0 = aB + kofA;
                    af[0] = lds32u(a0);
                    af[1] = lds32u(a0 + 32);
                    af[2] = lds32u(a0 + (uint32_t)(4 * APAD) * 4);
                    af[3] = lds32u(a0 + (uint32_t)(4 * APAD) * 4 + 32);
                }
#pragma unroll
                for (int mt = 0; mt < 4; mt++) {
                    uint32_t afn[4];
                    if (mt < 3) {
                        uint32_t an = aB + kofA + (uint32_t)((mt + 1) * 16) * 4;
                        afn[0] = lds32u(an);
                        afn[1] = lds32u(an + 32);
                        afn[2] = lds32u(an + (uint32_t)(4 * APAD) * 4);
                        afn[3] = lds32u(an + (uint32_t)(4 * APAD) * 4 + 32);
                    }
#pragma unroll
                    for (int jn = 0; jn < 8; jn++)
                        mma_tf32(acc[mt][jn], af, bf[jn]);
                    if (mt < 3) {
                        af[0] = afn[0]; af[1] = afn[1]; af[2] = afn[2]; af[3] = afn[3];
                    }
                }
            }
            __syncthreads();
        }

        // epilogue: dd = c2[n] - 2*dot; streaming top-2 per slot (n ascending ->
        // strict lexicographic keeps first occurrence, matching jnp.argmin)
#pragma unroll
        for (int jn = 0; jn < 8; jn++) {
            int n = t * BN + wn * 64 + jn * 8 + 2 * c;
            float2 c2v = __ldg(reinterpret_cast<const float2*>(g_c2 + n));
#pragma unroll
            for (int mt = 0; mt < 4; mt++) {
                float* d = acc[mt][jn];
#pragma unroll
                for (int q = 0; q < 4; q++) {
                    int s = 2 * mt + (q >> 1);
                    int nn = n + (q & 1);
                    float dd = fmaf(-2.f, d[q], (q & 1) ? c2v.y : c2v.x);
                    if (dd < v2[s] || (dd == v2[s] && nn < i2[s])) {
                        v2[s] = dd; i2[s] = nn;
                        if (v2[s] < v1[s] || (v2[s] == v1[s] && i2[s] < i1[s])) {
                            float tv = v1[s]; v1[s] = v2[s]; v2[s] = tv;
                            int   ti = i1[s]; i1[s] = i2[s]; i2[s] = ti;
                        }
                    }
                    d[q] = 0.f;
                }
            }
        }
    }

    // quad merge (lanes 4g..4g+3 share rows, own disjoint n) -> region top-2
#pragma unroll
    for (int s = 0; s < 8; s++) {
#pragma unroll
        for (int off = 1; off <= 2; off <<= 1) {
            float ov1 = __shfl_xor_sync(0xffffffffu, v1[s], off);
            int   oi1 = __shfl_xor_sync(0xffffffffu, i1[s], off);
            float ov2 = __shfl_xor_sync(0xffffffffu, v2[s], off);
            int   oi2 = __shfl_xor_sync(0xffffffffu, i2[s], off);
            bool ofirst = (ov1 < v1[s]) || (ov1 == v1[s] && oi1 < i1[s]);
            float nv1, nv2; int ni1, ni2;
            if (ofirst) {
                nv1 = ov1; ni1 = oi1;
                if (v1[s] < ov2 || (v1[s] == ov2 && i1[s] < oi2)) { nv2 = v1[s]; ni2 = i1[s]; }
                else                                               { nv2 = ov2;  ni2 = oi2;  }
            } else {
                nv1 = v1[s]; ni1 = i1[s];
                if (ov1 < v2[s] || (ov1 == v2[s] && oi1 < i2[s])) { nv2 = ov1;  ni2 = oi1;  }
                else                                               { nv2 = v2[s]; ni2 = i2[s]; }
            }
            v1[s] = nv1; i1[s] = ni1; v2[s] = nv2; i2[s] = ni2;
        }
        if (c == 0) {
            int row = m0 + wm * 64 + (s >> 1) * 16 + (s & 1) * 8 + g;
            g_cand_val[gy][row][wn * 2]     = v1[s];
            g_cand_idx[gy][row][wn * 2]     = i1[s];
            g_cand_val[gy][row][wn * 2 + 1] = v2[s];
            g_cand_idx[gy][row][wn * 2 + 1] = i2[s];
        }
    }
}

// ---------------- exact fp32 rescore of the 24 candidates per row ----------------
__global__ void rescore_kernel(const float* __restrict__ E, const float* __restrict__ C) {
    int r = blockIdx.x * 8 + (threadIdx.x >> 5);
    if (r >= M_ROWS) return;
    int lane = threadIdx.x & 31;
    float e[12];
#pragma unroll
    for (int i = 0; i < 12; i++) e[i] = __ldg(&E[(size_t)r * DD + lane + 32 * i]);
    float bv = finf(); int bi = 0x7fffffff;
#pragma unroll 1
    for (int cc = 0; cc < 3 * 8; cc++) {
        int n = g_cand_idx[cc >> 3][r][cc & 7];
        const float* cr = C + (size_t)n * DD;
        float dot = 0.f;
#pragma unroll
        for (int i = 0; i < 12; i++) dot = fmaf(e[i], __ldg(&cr[lane + 32 * i]), dot);
#pragma unroll
        for (int o = 16; o > 0; o >>= 1) dot += __shfl_xor_sync(0xffffffffu, dot, o);
        float dd = fmaf(-2.f, dot, __ldg(&g_c2[n]));
        if (dd < bv || (dd == bv && n < bi)) { bv = dd; bi = n; }
    }
    if (lane == 0) {
        g_score[r] = sqrtf(fmaxf(g_e2[r] + bv, 0.f));
        g_loc[r] = bi;
    }
}

// ---------------- per-batch argmax over P patches ----------------
__global__ void bargmax_kernel() {
    int b = blockIdx.x;
    int tid = threadIdx.x;
    float bv = -finf(); int bi = 0x7fffffff;
    for (int p = tid; p < PP; p += 256) {
        float v = g_score[b * PP + p];
        if (v > bv) { bv = v; bi = p; }   // strict > keeps first occurrence
    }
    __shared__ float sv[256]; __shared__ int si[256];
    sv[tid] = bv; si[tid] = bi;
    __syncthreads();
    for (int s = 128; s > 0; s >>= 1) {
        if (tid < s) {
            if (sv[tid + s] > sv[tid] ||
                (sv[tid + s] == sv[tid] && si[tid + s] < si[tid])) {
                sv[tid] = sv[tid + s]; si[tid] = si[tid + s];
            }
        }
        __syncthreads();
    }
    if (tid == 0) {
        g_bscore[b] = sv[0];
        g_bpatch[b] = si[0];
        g_bnn[b]    = g_loc[b * PP + si[0]];
    }
}

// ---------------- k-NN part 1: per-slice top-9 (grid 8 x 16 -> full chip) ----------------
__global__ void knn_part_kernel(const float* __restrict__ C) {
    int b = blockIdx.x, sl = blockIdx.y;
    int tid = threadIdx.x;
    __shared__ float nns[DD];
    __shared__ float cv[256 * NK];
    __shared__ int   ci[256 * NK];
    __shared__ float sv[256];
    __shared__ int   si[256];
    int nn = g_bnn[b];
    for (int k = tid; k < DD; k += 256) nns[k] = __ldg(&C[(size_t)nn * DD + k]);
    __syncthreads();
    float c2nn = g_c2[nn];

    float tv[NK]; int ti[NK];
#pragma unroll
    for (int q = 0; q < NK; q++) { tv[q] = finf(); ti[q] = 0x7fffffff; }

    int n_lo = sl * (N_CORE / KNN_SLICES), n_hi = n_lo + (N_CORE / KNN_SLICES);
    for (int n = n_lo + tid; n < n_hi; n += 256) {
        const float4* cr = reinterpret_cast<const float4*>(&C[(size_t)n * DD]);
        float dot = 0.f;
#pragma unroll 8
        for (int i = 0; i < DD / 4; i++) {
            float4 v = __ldg(&cr[i]);
            float4 u = *reinterpret_cast<const float4*>(&nns[i * 4]);
            dot = fmaf(v.x, u.x, dot);
            dot = fmaf(v.y, u.y, dot);
            dot = fmaf(v.z, u.z, dot);
            dot = fmaf(v.w, u.w, dot);
        }
        float dd = c2nn + g_c2[n] - 2.f * dot;   // sqrt monotonic -> compare d^2
        if (dd < tv[NK - 1]) {
            tv[NK - 1] = dd; ti[NK - 1] = n;
#pragma unroll
            for (int q = NK - 1; q > 0; q--) {
                if (tv[q] < tv[q - 1]) {
                    float a = tv[q]; tv[q] = tv[q - 1]; tv[q - 1] = a;
                    int   cc = ti[q]; ti[q] = ti[q - 1]; ti[q - 1] = cc;
                }
            }
        }
    }
#pragma unroll
    for (int q = 0; q < NK; q++) { cv[tid * NK + q] = tv[q]; ci[tid * NK + q] = ti[q]; }
    __syncthreads();

    for (int it = 0; it < NK; it++) {
        float bv = finf(); int bi = 0x7fffffff;
#pragma unroll
        for (int q = 0; q < NK; q++) {
            float v = cv[tid * NK + q]; int id = ci[tid * NK + q];
            if (v < bv || (v == bv && id < bi)) { bv = v; bi = id; }
        }
        sv[tid] = bv; si[tid] = bi;
        __syncthreads();
        for (int s = 128; s > 0; s >>= 1) {
            if (tid < s) {
                if (sv[tid + s] < sv[tid] ||
                    (sv[tid + s] == sv[tid] && si[tid + s] < si[tid])) {
                    sv[tid] = sv[tid + s]; si[tid] = si[tid + s];
                }
            }
            __syncthreads();
        }
        int wi = si[0];
        if (tid == 0) { g_pv[b][sl][it] = sv[0]; g_pi[b][sl][it] = wi; }
        __syncthreads();
#pragma unroll
        for (int q = 0; q < NK; q++)
            if (ci[tid * NK + q] == wi) cv[tid * NK + q] = finf();
        __syncthreads();
    }
}

// ---------------- k-NN part 2: merge 16x9 per-slice candidates -> top-9 ----------------
__global__ void knn_merge_kernel() {
    int b = blockIdx.x;
    int tid = threadIdx.x;   // 256 threads
    __shared__ float sv[256];
    __shared__ int   si[256];
    const int NCAND = KNN_SLICES * NK;   // 144
    float mv = finf(); int mi = 0x7fffffff;
    if (tid < NCAND) { mv = g_pv[b][tid / NK][tid % NK]; mi = g_pi[b][tid / NK][tid % NK]; }

    for (int it = 0; it < NK; it++) {
        sv[tid] = mv; si[tid] = mi;
        __syncthreads();
        for (int s = 128; s > 0; s >>= 1) {
            if (tid < s) {
                if (sv[tid + s] < sv[tid] ||
                    (sv[tid + s] == sv[tid] && si[tid + s] < si[tid])) {
                    sv[tid] = sv[tid + s]; si[tid] = si[tid + s];
                }
            }
            __syncthreads();
        }
        int wi = si[0];
        if (tid == 0) g_support[b][it] = wi;
        __syncthreads();
        if (mi == wi) mv = finf();
    }
}

// ---------------- final: d_sup, softmax, output ----------------
__global__ void final_kernel(const float* __restrict__ E, const float* __restrict__ C,
                             float* __restrict__ out) {
    int b = blockIdx.x;
    int tid = threadIdx.x;  // 128 threads
    __shared__ float qf[DD];
    __shared__ float dsup[NK];
    __shared__ float red[128];
    int m = b * PP + g_bpatch[b];
    for (int k = tid; k < DD; k += 128) qf[k] = __ldg(&E[(size_t)m * DD + k]);
    __syncthreads();
    float q2 = g_e2[m];
    for (int kk = 0; kk < NK; kk++) {
        int s = g_support[b][kk];
        float dot = 0.f;
        for (int k = tid; k < DD; k += 128)
            dot = fmaf(qf[k], __ldg(&C[(size_t)s * DD + k]), dot);
        red[tid] = dot;
        __syncthreads();
        for (int st = 64; st > 0; st >>= 1) {
            if (tid < st) red[tid] += red[tid + st];
            __syncthreads();
        }
        if (tid == 0) dsup[kk] = sqrtf(fmaxf(q2 + g_c2[s] - 2.f * red[0], 0.f));
        __syncthreads();
    }
    if (tid == 0) {
        float mx = dsup[0];
#pragma unroll
        for (int k = 1; k < NK; k++) mx = fmaxf(mx, dsup[k]);
        float se = 0.f, e0 = 0.f;
#pragma unroll
        for (int k = 0; k < NK; k++) {
            float e = expf(dsup[k] - mx);
            if (k == 0) e0 = e;
            se += e;
        }
        out[b] = (1.f - e0 / se) * g_bscore[b];
    }
}

// ---------------- launcher ----------------
extern "C" void kernel_launch(void* const* d_in, const int* in_sizes, int n_in,
                              void* d_out, int out_size) {
    const float* E = (const float*)d_in[0];   // [6272, 384]
    const float* C = (const float*)d_in[1];   // [16384, 384]
    float* out = (float*)d_out;               // [8]
    (void)in_sizes; (void)n_in; (void)out_size;

    cudaFuncSetAttribute(mindist_tc_kernel,
                         cudaFuncAttributeMaxDynamicSharedMemorySize, SMEM_T);

    norms_kernel<<<N_CORE, 128>>>(C, 0);
    norms_kernel<<<M_ROWS, 128>>>(E, 1);
    prep_kernel<<<dim3(64 + 25, KCHUNKS), 256>>>(E, C);
    mindist_tc_kernel<<<dim3(MBLKS, NSPLIT), 256, SMEM_T>>>();   // 4th launch -> ncu slot
    rescore_kernel<<<(M_ROWS + 7) / 8, 256>>>(E, C);
    bargmax_kernel<<<BSZ, 256>>>();
    knn_part_kernel<<<dim3(BSZ, KNN_SLICES), 256>>>(C);
    knn_merge_kernel<<<BSZ, 256>>>();
    final_kernel<<<BSZ, 128>>>(E, C, out);
}